// round 5
// baseline (speedup 1.0000x reference)
#include <cuda_runtime.h>
#include <cuda_bf16.h>
#include <math.h>

// ---------------------------------------------------------------------------
// Problem constants
// ---------------------------------------------------------------------------
constexpr int Bb = 64;          // batch
constexpr int Nn = 128;         // nodes
constexpr int Dd = 256;         // hidden dim
constexpr int Ee = 4;           // edge types
constexpr int STEPS = 5;
constexpr int ANNOT = 64;
constexpr int Mrows = Bb * Nn;  // 8192
constexpr int EN = Ee * Nn;     // 512

constexpr long long OFF_NODE = 0;
constexpr long long OFF_EDGE = (long long)Mrows * ANNOT;                 // 524288
constexpr long long OFF_MU   = OFF_EDGE + (long long)Mrows * EN;         // 4718592
constexpr long long OFF_VAR  = OFF_MU + (long long)Mrows * Dd;           // 6815744

// ---------------------------------------------------------------------------
// Device scratch (static allocations — allowed)
// ---------------------------------------------------------------------------
__device__ float g_h0[Mrows * Dd];
__device__ float g_h1[Mrows * Dd];
__device__ float g_inst[Bb * EN * Dd];   // (b, m=e*N+n, d) layout
__device__ float g_ain[Mrows * Dd];
__device__ float g_r[Mrows * Dd];
__device__ float g_z[Mrows * Dd];
__device__ float g_t1[Mrows * Dd];
__device__ float g_t2[Mrows * Dd];
__device__ float g_zlat[Mrows * Dd];
__device__ float g_eps[Mrows * Dd];

// ---------------------------------------------------------------------------
// JAX threefry2x32, key = jax.random.key(42) -> (0, 42)
// ---------------------------------------------------------------------------
__device__ __forceinline__ unsigned rotl32(unsigned x, int r) {
    return (x << r) | (x >> (32 - r));
}

__device__ __forceinline__ void threefry2x32_42(unsigned& x0, unsigned& x1) {
    const unsigned ks0 = 0u, ks1 = 42u, ks2 = 0u ^ 42u ^ 0x1BD11BDAu;
    const unsigned ks[3] = {ks0, ks1, ks2};
    x0 += ks[0]; x1 += ks[1];
    const int R0[4] = {13, 15, 26, 6};
    const int R1[4] = {17, 29, 16, 24};
#pragma unroll
    for (int i = 0; i < 5; i++) {
#pragma unroll
        for (int j = 0; j < 4; j++) {
            int r = (i % 2 == 0) ? R0[j] : R1[j];
            x0 += x1;
            x1 = rotl32(x1, r);
            x1 ^= x0;
        }
        x0 += ks[(i + 1) % 3];
        x1 += ks[(i + 2) % 3] + (unsigned)(i + 1);
    }
}

// XLA ErfInv float32 polynomial (matches jax lax.erf_inv on f32)
__device__ __forceinline__ float erfinv_xla(float x) {
    float w = -log1pf(-x * x);
    float p;
    if (w < 5.0f) {
        w = w - 2.5f;
        p = 2.81022636e-08f;
        p = fmaf(p, w, 3.43273939e-07f);
        p = fmaf(p, w, -3.5233877e-06f);
        p = fmaf(p, w, -4.39150654e-06f);
        p = fmaf(p, w, 0.00021858087f);
        p = fmaf(p, w, -0.00125372503f);
        p = fmaf(p, w, -0.00417768164f);
        p = fmaf(p, w, 0.246640727f);
        p = fmaf(p, w, 1.50140941f);
    } else {
        w = sqrtf(w) - 3.0f;
        p = -0.000200214257f;
        p = fmaf(p, w, 0.000100950558f);
        p = fmaf(p, w, 0.00134934322f);
        p = fmaf(p, w, -0.00367342844f);
        p = fmaf(p, w, 0.00573950773f);
        p = fmaf(p, w, -0.0076224613f);
        p = fmaf(p, w, 0.00943887047f);
        p = fmaf(p, w, 1.00167406f);
        p = fmaf(p, w, 2.83297682f);
    }
    return p * x;
}

__device__ __forceinline__ float bits_to_normal(unsigned bits) {
    // jax.random.uniform(lo=nextafter(-1,0), hi=1), then sqrt(2)*erfinv
    float f = __uint_as_float((bits >> 9) | 0x3f800000u) - 1.0f;
    const float lo = -0.99999994f;
    const float range = 1.0f - lo;   // rounds to 2.0f in f32, matching XLA
    float u = __fmul_rn(f, range);
    u = __fadd_rn(u, lo);
    u = fmaxf(lo, u);
    return 1.4142135f * erfinv_xla(u);
}

// Partitionable threefry: counter (hi,lo) = (0, i); out32 = lane0 ^ lane1.
__global__ void eps_kernel(float* __restrict__ eps) {
    unsigned i = blockIdx.x * blockDim.x + threadIdx.x;
    if (i >= (unsigned)(Mrows * Dd)) return;
    unsigned x0 = 0u, x1 = i;
    threefry2x32_42(x0, x1);
    eps[i] = bits_to_normal(x0 ^ x1);
}

// ---------------------------------------------------------------------------
// Tiled SGEMM: 128x128 block tile, BK=16, 256 threads, 8x8 per thread.
// Spec supplies loadA(row,k,bz), loadB(k,col,bz), store(row,col,v,bz).
// M, K must be multiples of 128/16; Ncols guarded (decode N=576).
// ---------------------------------------------------------------------------
template <class Spec>
__global__ void __launch_bounds__(256, 2) gemm_k(Spec s, int M, int Ncols, int K) {
    __shared__ __align__(16) float As[16][132];  // [k][m]
    __shared__ __align__(16) float Bs[16][132];  // [k][n]

    const int bz = blockIdx.z;
    const int row0 = blockIdx.y * 128;
    const int col0 = blockIdx.x * 128;
    const int tid = threadIdx.x;
    // A loader: 128 m x 16 k; thread -> (m = tid>>1, k0 = (tid&1)*8), 8 consecutive k
    const int am = tid >> 1, ak0 = (tid & 1) * 8;
    // B loader: 16 k x 128 n; thread -> (k = tid>>4, n0 = (tid&15)*8), 8 consecutive n
    const int bk = tid >> 4, bn0 = (tid & 15) * 8;
    // compute mapping: 16x16 thread grid, 8x8 microtile
    const int tx = tid & 15, ty = tid >> 4;

    float acc[8][8] = {};

    for (int k0 = 0; k0 < K; k0 += 16) {
#pragma unroll
        for (int i = 0; i < 8; i++)
            As[ak0 + i][am] = s.loadA(row0 + am, k0 + ak0 + i, bz);
#pragma unroll
        for (int i = 0; i < 8; i++) {
            int c = col0 + bn0 + i;
            Bs[bk][bn0 + i] = (c < Ncols) ? s.loadB(k0 + bk, c, bz) : 0.0f;
        }
        __syncthreads();
#pragma unroll
        for (int kk = 0; kk < 16; kk++) {
            float a[8], b[8];
            *(float4*)&a[0] = *(const float4*)&As[kk][ty * 8];
            *(float4*)&a[4] = *(const float4*)&As[kk][ty * 8 + 4];
            *(float4*)&b[0] = *(const float4*)&Bs[kk][tx * 8];
            *(float4*)&b[4] = *(const float4*)&Bs[kk][tx * 8 + 4];
#pragma unroll
            for (int i = 0; i < 8; i++)
#pragma unroll
                for (int j = 0; j < 8; j++)
                    acc[i][j] = fmaf(a[i], b[j], acc[i][j]);
        }
        __syncthreads();
    }

#pragma unroll
    for (int i = 0; i < 8; i++)
#pragma unroll
        for (int j = 0; j < 8; j++) {
            int c = col0 + tx * 8 + j;
            if (c < Ncols)
                s.store(row0 + ty * 8 + i, c, acc[i][j], bz);
        }
}

__device__ __forceinline__ float sigmoidf_(float x) { return 1.0f / (1.0f + expf(-x)); }

// --- Stage 1: in_states[b, e*N+n, f] = h[b,n,:] @ W_in[e] + b_in[e]  ---------
struct SpecInstates {
    const float* h; const float* W_in; const float* b_in; float* out;
    __device__ float loadA(int row, int k, int) const { return h[row * Dd + k]; }
    __device__ float loadB(int k, int col, int) const {
        int e = col >> 8, f = col & 255;
        return W_in[(e * Dd + k) * Dd + f];
    }
    __device__ void store(int row, int col, float v, int) const {
        int e = col >> 8, f = col & 255;
        int b = row >> 7, n = row & 127;
        out[((long long)b * EN + (e * Nn + n)) * Dd + f] = v + b_in[e * Dd + f];
    }
};

// --- Stage 2 (batched): a_in[b] = A_in[b] (128x512) @ in_states[b] (512x256) -
struct SpecAin {
    const float* A; const float* inst; float* out;
    __device__ float loadA(int row, int k, int b) const {
        return A[((long long)b * Nn + row) * (2 * EN) + k];
    }
    __device__ float loadB(int k, int col, int b) const {
        return inst[((long long)b * EN + k) * Dd + col];
    }
    __device__ void store(int row, int col, float v, int b) const {
        out[((long long)b * Nn + row) * Dd + col] = v;
    }
};

// --- Stage 3: r,z = sigmoid([a_in | h] @ [W_r | W_z] + [b_r | b_z]) ----------
struct SpecGates {
    const float* ain; const float* h;
    const float* W_r; const float* W_z; const float* b_r; const float* b_z;
    float* rb; float* zb;
    __device__ float loadA(int row, int k, int) const {
        return (k < Dd) ? ain[row * Dd + k] : h[row * Dd + (k - Dd)];
    }
    __device__ float loadB(int k, int col, int) const {
        return (col < Dd) ? W_r[k * Dd + col] : W_z[k * Dd + (col - Dd)];
    }
    __device__ void store(int row, int col, float v, int) const {
        if (col < Dd) rb[row * Dd + col] = sigmoidf_(v + b_r[col]);
        else          zb[row * Dd + (col - Dd)] = sigmoidf_(v + b_z[col - Dd]);
    }
};

// --- Stage 4: h_hat = tanh([a_in | r*h] @ W_t + b_t); h' = (1-z)h + z*h_hat --
struct SpecHhat {
    const float* ain; const float* rb; const float* hin;
    const float* W_t; const float* b_t; const float* zb;
    float* hout;
    __device__ float loadA(int row, int k, int) const {
        if (k < Dd) return ain[row * Dd + k];
        int idx = row * Dd + (k - Dd);
        return rb[idx] * hin[idx];
    }
    __device__ float loadB(int k, int col, int) const { return W_t[k * Dd + col]; }
    __device__ void store(int row, int col, float v, int) const {
        float hh = tanhf(v + b_t[col]);
        int idx = row * Dd + col;
        float z = zb[idx];
        hout[idx] = (1.0f - z) * hin[idx] + z * hh;
    }
};

// --- Head a: t1 = tanh(h@W_mu1+b), t2 = tanh(h@W_var1+b) ---------------------
struct SpecMuVarT {
    const float* h;
    const float* W1; const float* W2; const float* b1; const float* b2;
    float* t1; float* t2;
    __device__ float loadA(int row, int k, int) const { return h[row * Dd + k]; }
    __device__ float loadB(int k, int col, int) const {
        return (col < Dd) ? W1[k * Dd + col] : W2[k * Dd + (col - Dd)];
    }
    __device__ void store(int row, int col, float v, int) const {
        if (col < Dd) t1[row * Dd + col] = tanhf(v + b1[col]);
        else          t2[row * Dd + (col - Dd)] = tanhf(v + b2[col - Dd]);
    }
};

// --- Head b: plain linear: out = X @ W + b -----------------------------------
struct SpecLin {
    const float* X; const float* W; const float* bias; float* out;
    __device__ float loadA(int row, int k, int) const { return X[row * Dd + k]; }
    __device__ float loadB(int k, int col, int) const { return W[k * Dd + col]; }
    __device__ void store(int row, int col, float v, int) const {
        out[(long long)row * Dd + col] = v + bias[col];
    }
};

// --- Head d: node/edge decode: zlat @ [W_d1 | W_d2] --------------------------
struct SpecDecode {
    const float* zl;
    const float* W_d1; const float* W_d2; const float* b_d1; const float* b_d2;
    float* node; float* edge;
    __device__ float loadA(int row, int k, int) const { return zl[row * Dd + k]; }
    __device__ float loadB(int k, int col, int) const {
        return (col < ANNOT) ? W_d1[k * ANNOT + col] : W_d2[k * EN + (col - ANNOT)];
    }
    __device__ void store(int row, int col, float v, int) const {
        if (col < ANNOT) node[(long long)row * ANNOT + col] = v + b_d1[col];
        else             edge[(long long)row * EN + (col - ANNOT)] = v + b_d2[col - ANNOT];
    }
};

// --- zlat = eps * exp(0.5*var) + mu ------------------------------------------
__global__ void zlat_kernel(const float* __restrict__ eps,
                            const float* __restrict__ mu,
                            const float* __restrict__ var,
                            float* __restrict__ zl) {
    int i = blockIdx.x * blockDim.x + threadIdx.x;
    if (i >= Mrows * Dd) return;
    zl[i] = eps[i] * expf(0.5f * var[i]) + mu[i];
}

// ---------------------------------------------------------------------------
// Launch
// ---------------------------------------------------------------------------
extern "C" void kernel_launch(void* const* d_in, const int* in_sizes, int n_in,
                              void* d_out, int out_size) {
    const float* in[22];
    if (in_sizes[0] == Mrows * Dd) {
        for (int i = 0; i < 22; i++) in[i] = (const float*)d_in[i];
    } else {
        static const int alphaOfDict[22] = {21, 0, 3, 13, 6, 16, 10, 20, 7, 17,
                                            4, 14, 5, 15, 8, 18, 9, 19, 1, 11,
                                            2, 12};
        for (int i = 0; i < 22; i++) in[i] = (const float*)d_in[alphaOfDict[i]];
    }
    const float* prop  = in[0];
    const float* A     = in[1];
    const float* W_in  = in[2];
    const float* b_in  = in[3];
    const float* W_r   = in[4];
    const float* b_r   = in[5];
    const float* W_z   = in[6];
    const float* b_z   = in[7];
    const float* W_t   = in[8];
    const float* b_t   = in[9];
    const float* W_mu1 = in[10];
    const float* b_mu1 = in[11];
    const float* W_mu2 = in[12];
    const float* b_mu2 = in[13];
    const float* W_var1 = in[14];
    const float* b_var1 = in[15];
    const float* W_var2 = in[16];
    const float* b_var2 = in[17];
    const float* W_d1  = in[18];
    const float* b_d1  = in[19];
    const float* W_d2  = in[20];
    const float* b_d2  = in[21];
    float* out = (float*)d_out;

    float *h0, *h1, *inst, *ain, *rb, *zb, *t1, *t2, *zl, *eps;
    cudaGetSymbolAddress((void**)&h0, g_h0);
    cudaGetSymbolAddress((void**)&h1, g_h1);
    cudaGetSymbolAddress((void**)&inst, g_inst);
    cudaGetSymbolAddress((void**)&ain, g_ain);
    cudaGetSymbolAddress((void**)&rb, g_r);
    cudaGetSymbolAddress((void**)&zb, g_z);
    cudaGetSymbolAddress((void**)&t1, g_t1);
    cudaGetSymbolAddress((void**)&t2, g_t2);
    cudaGetSymbolAddress((void**)&zl, g_zlat);
    cudaGetSymbolAddress((void**)&eps, g_eps);

    // h0 <- prop_state
    cudaMemcpyAsync(h0, prop, (size_t)Mrows * Dd * sizeof(float),
                    cudaMemcpyDeviceToDevice);

    // eps (deterministic, input independent)
    eps_kernel<<<(Mrows * Dd + 255) / 256, 256>>>(eps);

    for (int step = 0; step < STEPS; step++) {
        float* hin  = (step % 2 == 0) ? h0 : h1;
        float* hout = (step % 2 == 0) ? h1 : h0;

        gemm_k<<<dim3(Ee * Dd / 128, Mrows / 128, 1), 256>>>(
            SpecInstates{hin, W_in, b_in, inst}, Mrows, Ee * Dd, Dd);

        gemm_k<<<dim3(Dd / 128, Nn / 128, Bb), 256>>>(
            SpecAin{A, inst, ain}, Nn, Dd, EN);

        gemm_k<<<dim3(2 * Dd / 128, Mrows / 128, 1), 256>>>(
            SpecGates{ain, hin, W_r, W_z, b_r, b_z, rb, zb}, Mrows, 2 * Dd, 2 * Dd);

        gemm_k<<<dim3(Dd / 128, Mrows / 128, 1), 256>>>(
            SpecHhat{ain, rb, hin, W_t, b_t, zb, hout}, Mrows, Dd, 2 * Dd);
    }
    float* hfin = h1;  // STEPS=5 -> ends in h1

    gemm_k<<<dim3(2 * Dd / 128, Mrows / 128, 1), 256>>>(
        SpecMuVarT{hfin, W_mu1, W_var1, b_mu1, b_var1, t1, t2}, Mrows, 2 * Dd, Dd);

    gemm_k<<<dim3(Dd / 128, Mrows / 128, 1), 256>>>(
        SpecLin{t1, W_mu2, b_mu2, out + OFF_MU}, Mrows, Dd, Dd);

    gemm_k<<<dim3(Dd / 128, Mrows / 128, 1), 256>>>(
        SpecLin{t2, W_var2, b_var2, out + OFF_VAR}, Mrows, Dd, Dd);

    zlat_kernel<<<(Mrows * Dd + 255) / 256, 256>>>(eps, out + OFF_MU,
                                                   out + OFF_VAR, zl);

    gemm_k<<<dim3((ANNOT + EN + 127) / 128, Mrows / 128, 1), 256>>>(
        SpecDecode{zl, W_d1, W_d2, b_d1, b_d2, out + OFF_NODE, out + OFF_EDGE},
        Mrows, ANNOT + EN, Dd);
}

// round 7
// speedup vs baseline: 2.5828x; 2.5828x over previous
#include <cuda_runtime.h>
#include <cuda_bf16.h>
#include <math.h>
#include <stdint.h>

using bf16 = __nv_bfloat16;

// ---------------------------------------------------------------------------
// Problem constants
// ---------------------------------------------------------------------------
constexpr int Bb = 64, Nn = 128, Dd = 256, Ee = 4, STEPS = 5, ANNOT = 64;
constexpr int Mrows = Bb * Nn;   // 8192
constexpr int EN = Ee * Nn;      // 512

constexpr long long OFF_NODE = 0;
constexpr long long OFF_EDGE = (long long)Mrows * ANNOT;
constexpr long long OFF_MU   = OFF_EDGE + (long long)Mrows * EN;
constexpr long long OFF_VAR  = OFF_MU + (long long)Mrows * Dd;

// ---------------------------------------------------------------------------
// Device scratch (static — allowed)
// ---------------------------------------------------------------------------
__device__ float g_h[Mrows * Dd];
__device__ float g_zb[Mrows * Dd];
__device__ float g_eps[Mrows * Dd];
__device__ bf16 g_hH[Mrows * Dd],  g_hL[Mrows * Dd];
__device__ bf16 g_ainH[Mrows * Dd], g_ainL[Mrows * Dd];
__device__ bf16 g_rhH[Mrows * Dd],  g_rhL[Mrows * Dd];
__device__ bf16 g_t1H[Mrows * Dd],  g_t1L[Mrows * Dd];
__device__ bf16 g_t2H[Mrows * Dd],  g_t2L[Mrows * Dd];
__device__ bf16 g_zlH[Mrows * Dd],  g_zlL[Mrows * Dd];
__device__ bf16 g_iTH[Bb * Dd * EN], g_iTL[Bb * Dd * EN];   // [b][d][m]
__device__ bf16 g_AinH[Mrows * EN],  g_AinL[Mrows * EN];    // [b*128+n][512]
// Transposed bf16 weights, [n][k]
__device__ bf16 g_WinTH[Ee * Dd * Dd], g_WinTL[Ee * Dd * Dd];
__device__ bf16 g_WrzTH[512 * 512],    g_WrzTL[512 * 512];
__device__ bf16 g_WtTH[256 * 512],     g_WtTL[256 * 512];
__device__ bf16 g_WmvTH[512 * 256],    g_WmvTL[512 * 256];
__device__ bf16 g_Wmu2TH[256 * 256],   g_Wmu2TL[256 * 256];
__device__ bf16 g_Wvr2TH[256 * 256],   g_Wvr2TL[256 * 256];
__device__ bf16 g_WdTH[576 * 256],     g_WdTL[576 * 256];

// ---------------------------------------------------------------------------
// helpers
// ---------------------------------------------------------------------------
__device__ __forceinline__ uint32_t smem_u32(const void* p) {
    uint32_t a;
    asm("{ .reg .u64 t; cvta.to.shared.u64 t, %1; cvt.u32.u64 %0, t; }" : "=r"(a) : "l"(p));
    return a;
}
__device__ __forceinline__ void ldsm4(uint32_t& r0, uint32_t& r1, uint32_t& r2,
                                      uint32_t& r3, uint32_t addr) {
    asm volatile("ldmatrix.sync.aligned.m8n8.x4.shared.b16 {%0,%1,%2,%3}, [%4];"
                 : "=r"(r0), "=r"(r1), "=r"(r2), "=r"(r3) : "r"(addr));
}
__device__ __forceinline__ void mma16816(float& c0, float& c1, float& c2, float& c3,
                                         uint32_t a0, uint32_t a1, uint32_t a2,
                                         uint32_t a3, uint32_t b0, uint32_t b1) {
    asm volatile(
        "mma.sync.aligned.m16n8k16.row.col.f32.bf16.bf16.f32 "
        "{%0,%1,%2,%3},{%4,%5,%6,%7},{%8,%9},{%0,%1,%2,%3};"
        : "+f"(c0), "+f"(c1), "+f"(c2), "+f"(c3)
        : "r"(a0), "r"(a1), "r"(a2), "r"(a3), "r"(b0), "r"(b1));
}
__device__ __forceinline__ void split2(float v, bf16& h, bf16& l) {
    h = __float2bfloat16(v);
    l = __float2bfloat16(v - __bfloat162float(h));
}
__device__ __forceinline__ float sigmoidf_(float x) { return 1.0f / (1.0f + expf(-x)); }

// ---------------------------------------------------------------------------
// mma_gemm: D(128 x 64) = A(128 x K) @ B(64 x K)^T, split-bf16 (3 products),
// fp32 accum. mma.sync.m16n8k16, ldmatrix, XOR-swizzled smem (BK=32).
// Spec: aH/aL(row,k0,bz), bH/bL(col,k0,bz) -> ptr to 32 contiguous bf16;
//       store(row,col,v,bz).
// smem element (row, vec v of 8 bf16): offset = row*32 + (v ^ ((row>>1)&3))*8
// -> conflict-free for 16B fills and all ldmatrix groups.
// ---------------------------------------------------------------------------
template <class Spec>
__global__ void __launch_bounds__(256, 2) mma_gemm(Spec s, int K) {
    __shared__ __align__(16) bf16 AsH[128 * 32], AsL[128 * 32];
    __shared__ __align__(16) bf16 BsH[64 * 32],  BsL[64 * 32];

    const int tid = threadIdx.x;
    const int lane = tid & 31, wid = tid >> 5;
    const int wm = wid >> 1, wn = wid & 1;            // warp grid 4 x 2
    const int row0 = blockIdx.y * 128, col0 = blockIdx.x * 64, bz = blockIdx.z;

    const uint32_t aH32 = smem_u32(AsH), aL32 = smem_u32(AsL);
    const uint32_t bH32 = smem_u32(BsH), bL32 = smem_u32(BsL);

    float acc[2][4][4] = {};

    // ldmatrix lane-row constants
    const int a_lrow = lane & 15;            // A: row within 16-row tile
    const int a_khi  = (lane >= 16) ? 1 : 0; // A: +8 k for groups 2,3
    const int b_lrow = (lane & 7) + ((lane >= 16) ? 8 : 0);  // B: n within 16
    const int b_khi  = (lane & 8) ? 1 : 0;                    // B: +8 k

    for (int k0 = 0; k0 < K; k0 += 32) {
        // cooperative fill: 1536 16B-vector jobs
#pragma unroll
        for (int p = 0; p < 6; p++) {
            int j = p * 256 + tid;
            const bf16* src;
            bf16* dst;
            int row, v;
            if (j < 512) {
                row = j >> 2; v = j & 3;
                src = s.aH(row0 + row, k0, bz);
                dst = AsH;
            } else if (j < 1024) {
                int l = j - 512; row = l >> 2; v = l & 3;
                src = s.aL(row0 + row, k0, bz);
                dst = AsL;
            } else if (j < 1280) {
                int l = j - 1024; row = l >> 2; v = l & 3;
                src = s.bH(col0 + row, k0, bz);
                dst = BsH;
            } else {
                int l = j - 1280; row = l >> 2; v = l & 3;
                src = s.bL(col0 + row, k0, bz);
                dst = BsL;
            }
            int sv = v ^ ((row >> 1) & 3);
            *(uint4*)(dst + row * 32 + sv * 8) = *(const uint4*)(src + v * 8);
        }
        __syncthreads();

#pragma unroll
        for (int ks = 0; ks < 2; ks++) {
            uint32_t ah[2][4], al[2][4], bh[4][2], bl[4][2];
            // A fragments (two 16-row tiles)
#pragma unroll
            for (int mt = 0; mt < 2; mt++) {
                int r = wm * 32 + mt * 16 + a_lrow;
                int kv = ks * 2 + a_khi;
                uint32_t off = (uint32_t)(r * 32 + ((kv ^ ((r >> 1) & 3)) * 8)) * 2;
                ldsm4(ah[mt][0], ah[mt][1], ah[mt][2], ah[mt][3], aH32 + off);
                ldsm4(al[mt][0], al[mt][1], al[mt][2], al[mt][3], aL32 + off);
            }
            // B fragments (two 16-n groups -> 4 n8 tiles)
#pragma unroll
            for (int ng = 0; ng < 2; ng++) {
                int r = wn * 32 + ng * 16 + b_lrow;
                int kv = ks * 2 + b_khi;
                uint32_t off = (uint32_t)(r * 32 + ((kv ^ ((r >> 1) & 3)) * 8)) * 2;
                uint32_t r0, r1, r2, r3;
                ldsm4(r0, r1, r2, r3, bH32 + off);
                bh[ng * 2][0] = r0; bh[ng * 2][1] = r1;
                bh[ng * 2 + 1][0] = r2; bh[ng * 2 + 1][1] = r3;
                ldsm4(r0, r1, r2, r3, bL32 + off);
                bl[ng * 2][0] = r0; bl[ng * 2][1] = r1;
                bl[ng * 2 + 1][0] = r2; bl[ng * 2 + 1][1] = r3;
            }
#pragma unroll
            for (int mt = 0; mt < 2; mt++)
#pragma unroll
                for (int nt = 0; nt < 4; nt++) {
                    float* c = acc[mt][nt];
                    mma16816(c[0], c[1], c[2], c[3],
                             ah[mt][0], ah[mt][1], ah[mt][2], ah[mt][3],
                             bh[nt][0], bh[nt][1]);
                    mma16816(c[0], c[1], c[2], c[3],
                             ah[mt][0], ah[mt][1], ah[mt][2], ah[mt][3],
                             bl[nt][0], bl[nt][1]);
                    mma16816(c[0], c[1], c[2], c[3],
                             al[mt][0], al[mt][1], al[mt][2], al[mt][3],
                             bh[nt][0], bh[nt][1]);
                }
        }
        __syncthreads();
    }

    // epilogue: c0 (r, c), c1 (r, c+1), c2 (r+8, c), c3 (r+8, c+1)
    const int er = lane >> 2, ec = (lane & 3) * 2;
#pragma unroll
    for (int mt = 0; mt < 2; mt++)
#pragma unroll
        for (int nt = 0; nt < 4; nt++) {
            int r = row0 + wm * 32 + mt * 16 + er;
            int c = col0 + wn * 32 + nt * 8 + ec;
            s.store(r,     c,     acc[mt][nt][0], bz);
            s.store(r,     c + 1, acc[mt][nt][1], bz);
            s.store(r + 8, c,     acc[mt][nt][2], bz);
            s.store(r + 8, c + 1, acc[mt][nt][3], bz);
        }
}

// ---------------------------------------------------------------------------
// Specs (A row ptr must have 32 valid contiguous bf16 at (row, k0))
// ---------------------------------------------------------------------------
// 1) in_states: A=h (8192x256), B=WinT (1024x256); write instT hi/lo [b][d][m]
struct TS1 {
    const bf16 *hH, *hL, *WH, *WL; const float* b_in; bf16 *iTH, *iTL;
    __device__ const bf16* aH(int r, int k0, int) const { return hH + r * 256 + k0; }
    __device__ const bf16* aL(int r, int k0, int) const { return hL + r * 256 + k0; }
    __device__ const bf16* bH(int n, int k0, int) const { return WH + n * 256 + k0; }
    __device__ const bf16* bL(int n, int k0, int) const { return WL + n * 256 + k0; }
    __device__ void store(int row, int col, float v, int) const {
        int e = col >> 8, f = col & 255, b = row >> 7, nn = row & 127;
        float val = v + b_in[e * 256 + f];
        long idx = ((long)(b * 256 + f)) * 512 + e * 128 + nn;
        split2(val, iTH[idx], iTL[idx]);
    }
};
// 2) a_in (batched): A=A_in[b] (128x512), B=instT[b] (256x512)
struct TS2 {
    const bf16 *AiH, *AiL, *iTH, *iTL; bf16 *aoH, *aoL;
    __device__ const bf16* aH(int r, int k0, int b) const { return AiH + ((long)(b * 128 + r)) * 512 + k0; }
    __device__ const bf16* aL(int r, int k0, int b) const { return AiL + ((long)(b * 128 + r)) * 512 + k0; }
    __device__ const bf16* bH(int n, int k0, int b) const { return iTH + ((long)(b * 256 + n)) * 512 + k0; }
    __device__ const bf16* bL(int n, int k0, int b) const { return iTL + ((long)(b * 256 + n)) * 512 + k0; }
    __device__ void store(int row, int col, float v, int b) const {
        long idx = ((long)(b * 128 + row)) * 256 + col;
        split2(v, aoH[idx], aoL[idx]);
    }
};
// 3) gates: A=[ain|h] (8192x512), B=WrzT (512x512); rh hi/lo + z fp32
struct TS3 {
    const bf16 *anH, *anL, *hH, *hL, *WH, *WL;
    const float *b_r, *b_z, *hf; bf16 *rhH, *rhL; float* zb;
    __device__ const bf16* aH(int r, int k0, int) const {
        return k0 < 256 ? anH + r * 256 + k0 : hH + r * 256 + k0 - 256;
    }
    __device__ const bf16* aL(int r, int k0, int) const {
        return k0 < 256 ? anL + r * 256 + k0 : hL + r * 256 + k0 - 256;
    }
    __device__ const bf16* bH(int n, int k0, int) const { return WH + n * 512 + k0; }
    __device__ const bf16* bL(int n, int k0, int) const { return WL + n * 512 + k0; }
    __device__ void store(int row, int col, float v, int) const {
        if (col < 256) {
            float r = sigmoidf_(v + b_r[col]);
            long idx = (long)row * 256 + col;
            split2(r * hf[idx], rhH[idx], rhL[idx]);
        } else {
            zb[(long)row * 256 + col - 256] = sigmoidf_(v + b_z[col - 256]);
        }
    }
};
// 4) h_hat + GRU update: A=[ain|rh] (8192x512), B=WtT (256x512)
struct TS4 {
    const bf16 *anH, *anL, *rhH, *rhL, *WH, *WL;
    const float *b_t, *zb; float* hf; bf16 *hH, *hL;
    __device__ const bf16* aH(int r, int k0, int) const {
        return k0 < 256 ? anH + r * 256 + k0 : rhH + r * 256 + k0 - 256;
    }
    __device__ const bf16* aL(int r, int k0, int) const {
        return k0 < 256 ? anL + r * 256 + k0 : rhL + r * 256 + k0 - 256;
    }
    __device__ const bf16* bH(int n, int k0, int) const { return WH + n * 512 + k0; }
    __device__ const bf16* bL(int n, int k0, int) const { return WL + n * 512 + k0; }
    __device__ void store(int row, int col, float v, int) const {
        float hh = tanhf(v + b_t[col]);
        long idx = (long)row * 256 + col;
        float z = zb[idx];
        float hn = (1.0f - z) * hf[idx] + z * hh;
        hf[idx] = hn;
        split2(hn, hH[idx], hL[idx]);
    }
};
// 5) heads tanh: A=h, B=WmvT (512x256)
struct TS5 {
    const bf16 *hH, *hL, *WH, *WL; const float *b1, *b2;
    bf16 *t1H, *t1L, *t2H, *t2L;
    __device__ const bf16* aH(int r, int k0, int) const { return hH + r * 256 + k0; }
    __device__ const bf16* aL(int r, int k0, int) const { return hL + r * 256 + k0; }
    __device__ const bf16* bH(int n, int k0, int) const { return WH + n * 256 + k0; }
    __device__ const bf16* bL(int n, int k0, int) const { return WL + n * 256 + k0; }
    __device__ void store(int row, int col, float v, int) const {
        if (col < 256) {
            float t = tanhf(v + b1[col]);
            long idx = (long)row * 256 + col;
            split2(t, t1H[idx], t1L[idx]);
        } else {
            float t = tanhf(v + b2[col - 256]);
            long idx = (long)row * 256 + col - 256;
            split2(t, t2H[idx], t2L[idx]);
        }
    }
};
// 6) plain linear to fp32 out
struct TS6 {
    const bf16 *XH, *XL, *WH, *WL; const float* bias; float* out;
    __device__ const bf16* aH(int r, int k0, int) const { return XH + r * 256 + k0; }
    __device__ const bf16* aL(int r, int k0, int) const { return XL + r * 256 + k0; }
    __device__ const bf16* bH(int n, int k0, int) const { return WH + n * 256 + k0; }
    __device__ const bf16* bL(int n, int k0, int) const { return WL + n * 256 + k0; }
    __device__ void store(int row, int col, float v, int) const {
        out[(long)row * 256 + col] = v + bias[col];
    }
};
// 7) decode: A=zlat, B=WdT (576x256)
struct TS8 {
    const bf16 *XH, *XL, *WH, *WL; const float *b_d1, *b_d2;
    float *node, *edge;
    __device__ const bf16* aH(int r, int k0, int) const { return XH + r * 256 + k0; }
    __device__ const bf16* aL(int r, int k0, int) const { return XL + r * 256 + k0; }
    __device__ const bf16* bH(int n, int k0, int) const { return WH + n * 256 + k0; }
    __device__ const bf16* bL(int n, int k0, int) const { return WL + n * 256 + k0; }
    __device__ void store(int row, int col, float v, int) const {
        if (col < 64) node[(long)row * 64 + col] = v + b_d1[col];
        else          edge[(long)row * 512 + col - 64] = v + b_d2[col - 64];
    }
};

// ---------------------------------------------------------------------------
// Elementwise kernels
// ---------------------------------------------------------------------------
__device__ __forceinline__ unsigned rotl32(unsigned x, int r) { return (x << r) | (x >> (32 - r)); }
__device__ __forceinline__ void threefry2x32_42(unsigned& x0, unsigned& x1) {
    const unsigned ks[3] = {0u, 42u, 0u ^ 42u ^ 0x1BD11BDAu};
    x0 += ks[0]; x1 += ks[1];
    const int R0[4] = {13, 15, 26, 6}, R1[4] = {17, 29, 16, 24};
#pragma unroll
    for (int i = 0; i < 5; i++) {
#pragma unroll
        for (int j = 0; j < 4; j++) {
            int r = (i % 2 == 0) ? R0[j] : R1[j];
            x0 += x1; x1 = rotl32(x1, r); x1 ^= x0;
        }
        x0 += ks[(i + 1) % 3];
        x1 += ks[(i + 2) % 3] + (unsigned)(i + 1);
    }
}
__device__ __forceinline__ float erfinv_xla(float x) {
    float w = -log1pf(-x * x), p;
    if (w < 5.0f) {
        w = w - 2.5f;
        p = 2.81022636e-08f;
        p = fmaf(p, w, 3.43273939e-07f);  p = fmaf(p, w, -3.5233877e-06f);
        p = fmaf(p, w, -4.39150654e-06f); p = fmaf(p, w, 0.00021858087f);
        p = fmaf(p, w, -0.00125372503f);  p = fmaf(p, w, -0.00417768164f);
        p = fmaf(p, w, 0.246640727f);     p = fmaf(p, w, 1.50140941f);
    } else {
        w = sqrtf(w) - 3.0f;
        p = -0.000200214257f;
        p = fmaf(p, w, 0.000100950558f);  p = fmaf(p, w, 0.00134934322f);
        p = fmaf(p, w, -0.00367342844f);  p = fmaf(p, w, 0.00573950773f);
        p = fmaf(p, w, -0.0076224613f);   p = fmaf(p, w, 0.00943887047f);
        p = fmaf(p, w, 1.00167406f);      p = fmaf(p, w, 2.83297682f);
    }
    return p * x;
}
__device__ __forceinline__ float bits_to_normal(unsigned bits) {
    float f = __uint_as_float((bits >> 9) | 0x3f800000u) - 1.0f;
    const float lo = -0.99999994f;
    float u = __fmul_rn(f, 1.0f - lo);
    u = __fadd_rn(u, lo);
    u = fmaxf(lo, u);
    return 1.4142135f * erfinv_xla(u);
}
__global__ void eps_kernel(float* __restrict__ eps) {
    unsigned i = blockIdx.x * blockDim.x + threadIdx.x;
    if (i >= (unsigned)(Mrows * Dd)) return;
    unsigned x0 = 0u, x1 = i;
    threefry2x32_42(x0, x1);
    eps[i] = bits_to_normal(x0 ^ x1);   // partitionable: lane0 ^ lane1
}
__global__ void convT_k(const float* __restrict__ src, bf16* __restrict__ hi,
                        bf16* __restrict__ lo, int K, int N) {
    int i = blockIdx.x * blockDim.x + threadIdx.x;
    if (i >= K * N) return;
    int k = i / N, n = i % N;
    float v = src[i];
    bf16 h = __float2bfloat16(v);
    hi[(long)n * K + k] = h;
    lo[(long)n * K + k] = __float2bfloat16(v - __bfloat162float(h));
}
__global__ void convRows_k(const float* __restrict__ src, long stride,
                           bf16* __restrict__ hi, bf16* __restrict__ lo,
                           int R, int K) {
    long i = (long)blockIdx.x * blockDim.x + threadIdx.x;
    if (i >= (long)R * K) return;
    long r = i / K, k = i - r * K;
    float v = src[r * stride + k];
    bf16 h = __float2bfloat16(v);
    hi[i] = h;
    lo[i] = __float2bfloat16(v - __bfloat162float(h));
}
__global__ void zlat_k(const float* __restrict__ eps, const float* __restrict__ mu,
                       const float* __restrict__ var, bf16* __restrict__ zh,
                       bf16* __restrict__ zl) {
    int i = blockIdx.x * blockDim.x + threadIdx.x;
    if (i >= Mrows * Dd) return;
    float v = eps[i] * expf(0.5f * var[i]) + mu[i];
    bf16 h = __float2bfloat16(v);
    zh[i] = h;
    zl[i] = __float2bfloat16(v - __bfloat162float(h));
}

// ---------------------------------------------------------------------------
// Launch
// ---------------------------------------------------------------------------
#define GETSYM(var, sym) cudaGetSymbolAddress((void**)&var, sym)

extern "C" void kernel_launch(void* const* d_in, const int* in_sizes, int n_in,
                              void* d_out, int out_size) {
    const float* in[22];
    if (in_sizes[0] == Mrows * Dd) {
        for (int i = 0; i < 22; i++) in[i] = (const float*)d_in[i];
    } else {
        static const int alphaOfDict[22] = {21, 0, 3, 13, 6, 16, 10, 20, 7, 17,
                                            4, 14, 5, 15, 8, 18, 9, 19, 1, 11, 2, 12};
        for (int i = 0; i < 22; i++) in[i] = (const float*)d_in[alphaOfDict[i]];
    }
    const float *prop = in[0], *A = in[1], *W_in = in[2], *b_in = in[3];
    const float *W_r = in[4], *b_r = in[5], *W_z = in[6], *b_z = in[7];
    const float *W_t = in[8], *b_t = in[9];
    const float *W_mu1 = in[10], *b_mu1 = in[11], *W_mu2 = in[12], *b_mu2 = in[13];
    const float *W_var1 = in[14], *b_var1 = in[15], *W_var2 = in[16], *b_var2 = in[17];
    const float *W_d1 = in[18], *b_d1 = in[19], *W_d2 = in[20], *b_d2 = in[21];
    float* out = (float*)d_out;

    float *hf, *zb, *eps;
    bf16 *hH, *hL, *anH, *anL, *rhH, *rhL, *t1H, *t1L, *t2H, *t2L, *zlH, *zlL;
    bf16 *iTH, *iTL, *AiH, *AiL;
    bf16 *WinTH, *WinTL, *WrzTH, *WrzTL, *WtTH, *WtTL, *WmvTH, *WmvTL;
    bf16 *Wmu2TH, *Wmu2TL, *Wvr2TH, *Wvr2TL, *WdTH, *WdTL;
    GETSYM(hf, g_h); GETSYM(zb, g_zb); GETSYM(eps, g_eps);
    GETSYM(hH, g_hH); GETSYM(hL, g_hL); GETSYM(anH, g_ainH); GETSYM(anL, g_ainL);
    GETSYM(rhH, g_rhH); GETSYM(rhL, g_rhL);
    GETSYM(t1H, g_t1H); GETSYM(t1L, g_t1L); GETSYM(t2H, g_t2H); GETSYM(t2L, g_t2L);
    GETSYM(zlH, g_zlH); GETSYM(zlL, g_zlL);
    GETSYM(iTH, g_iTH); GETSYM(iTL, g_iTL); GETSYM(AiH, g_AinH); GETSYM(AiL, g_AinL);
    GETSYM(WinTH, g_WinTH); GETSYM(WinTL, g_WinTL);
    GETSYM(WrzTH, g_WrzTH); GETSYM(WrzTL, g_WrzTL);
    GETSYM(WtTH, g_WtTH); GETSYM(WtTL, g_WtTL);
    GETSYM(WmvTH, g_WmvTH); GETSYM(WmvTL, g_WmvTL);
    GETSYM(Wmu2TH, g_Wmu2TH); GETSYM(Wmu2TL, g_Wmu2TL);
    GETSYM(Wvr2TH, g_Wvr2TH); GETSYM(Wvr2TL, g_Wvr2TL);
    GETSYM(WdTH, g_WdTH); GETSYM(WdTL, g_WdTL);

    // h0 (fp32 + split), eps, A_in split
    cudaMemcpyAsync(hf, prop, (size_t)Mrows * Dd * sizeof(float), cudaMemcpyDeviceToDevice);
    eps_kernel<<<(Mrows * Dd + 255) / 256, 256>>>(eps);
    convRows_k<<<((long)Mrows * Dd + 255) / 256, 256>>>(prop, 256, hH, hL, Mrows, 256);
    convRows_k<<<((long)Mrows * EN + 255) / 256, 256>>>(A, 1024, AiH, AiL, Mrows, 512);

    // weights -> transposed bf16 hi/lo
    for (int e = 0; e < 4; e++)
        convT_k<<<(65536 + 255) / 256, 256>>>(W_in + e * 65536, WinTH + e * 65536,
                                              WinTL + e * 65536, 256, 256);
    convT_k<<<(131072 + 255) / 256, 256>>>(W_r, WrzTH, WrzTL, 512, 256);
    convT_k<<<(131072 + 255) / 256, 256>>>(W_z, WrzTH + 256 * 512, WrzTL + 256 * 512, 512, 256);
    convT_k<<<(131072 + 255) / 256, 256>>>(W_t, WtTH, WtTL, 512, 256);
    convT_k<<<(65536 + 255) / 256, 256>>>(W_mu1, WmvTH, WmvTL, 256, 256);
    convT_k<<<(65536 + 255) / 256, 256>>>(W_var1, WmvTH + 256 * 256, WmvTL + 256 * 256, 256, 256);
    convT_k<<<(65536 + 255) / 256, 256>>>(W_mu2, Wmu2TH, Wmu2TL, 256, 256);
    convT_k<<<(65536 + 255) / 256, 256>>>(W_var2, Wvr2TH, Wvr2TL, 256, 256);
    convT_k<<<(16384 + 255) / 256, 256>>>(W_d1, WdTH, WdTL, 256, 64);
    convT_k<<<(131072 + 255) / 256, 256>>>(W_d2, WdTH + 64 * 256, WdTL + 64 * 256, 256, 512);

    for (int step = 0; step < STEPS; step++) {
        mma_gemm<TS1><<<dim3(16, 64, 1), 256>>>(
            TS1{hH, hL, WinTH, WinTL, b_in, iTH, iTL}, 256);
        mma_gemm<TS2><<<dim3(4, 1, 64), 256>>>(
            TS2{AiH, AiL, iTH, iTL, anH, anL}, 512);
        mma_gemm<TS3><<<dim3(8, 64, 1), 256>>>(
            TS3{anH, anL, hH, hL, WrzTH, WrzTL, b_r, b_z, hf, rhH, rhL, zb}, 512);
        mma_gemm<TS4><<<dim3(4, 64, 1), 256>>>(
            TS4{anH, anL, rhH, rhL, WtTH, WtTL, b_t, zb, hf, hH, hL}, 512);
    }

    mma_gemm<TS5><<<dim3(8, 64, 1), 256>>>(
        TS5{hH, hL, WmvTH, WmvTL, b_mu1, b_var1, t1H, t1L, t2H, t2L}, 256);
    mma_gemm<TS6><<<dim3(4, 64, 1), 256>>>(
        TS6{t1H, t1L, Wmu2TH, Wmu2TL, b_mu2, out + OFF_MU}, 256);
    mma_gemm<TS6><<<dim3(4, 64, 1), 256>>>(
        TS6{t2H, t2L, Wvr2TH, Wvr2TL, b_var2, out + OFF_VAR}, 256);
    zlat_k<<<(Mrows * Dd + 255) / 256, 256>>>(eps, out + OFF_MU, out + OFF_VAR, zlH, zlL);
    mma_gemm<TS8><<<dim3(9, 64, 1), 256>>>(
        TS8{zlH, zlL, WdTH, WdTL, b_d1, b_d2, out + OFF_NODE, out + OFF_EDGE}, 256);
}